// round 2
// baseline (speedup 1.0000x reference)
#include <cuda_runtime.h>

// PositionalEncoding: out[b,t,i] = x[b,t,i] + P[t,i]
//   P[2f,   i] = sin(f / 10000^(2i/F))
//   P[2f+1, i] = cos(f / 10000^(2i/F))
// x: [32, 2048, 1024] fp32. HBM-streaming-bound (512MB floor).
// R2: higher occupancy (no 4-CTA cap), grid.y=4 batch split for finer
// load balance, and streaming cache hints (.cs) on the once-touched data.

#define PE_T 2048
#define PE_F 1024
#define PE_B 32
#define PE_BY 4                      // batch slices per grid.y
#define PE_BPER (PE_B / PE_BY)       // 8 batches per thread

__global__ __launch_bounds__(256)
void pe_add_kernel(const float* __restrict__ x, float* __restrict__ out) {
    const int t = blockIdx.x;          // row 0..2047
    const int c = threadIdx.x;         // float4 column 0..255
    const int b0 = blockIdx.y * PE_BPER;

    const float f = (float)(t >> 1);
    const bool is_sin = (t & 1) == 0;

    float pv[4];
#pragma unroll
    for (int k = 0; k < 4; k++) {
        const int i = c * 4 + k;
        const float e = (float)i * (1.0f / 512.0f);   // 2*i/F, exact in fp32
        const float den = powf(10000.0f, e);
        const float ang = f / den;
        pv[k] = is_sin ? sinf(ang) : cosf(ang);
    }
    const float4 p = make_float4(pv[0], pv[1], pv[2], pv[3]);

    const float4* __restrict__ x4 = (const float4*)x;
    float4* __restrict__ o4 = (float4*)out;
    const size_t row_stride4 = (size_t)PE_T * (PE_F / 4);   // float4 per batch slice
    const size_t base = (size_t)t * (PE_F / 4) + (size_t)c
                      + (size_t)b0 * row_stride4;

#pragma unroll
    for (int b = 0; b < PE_BPER; b++) {
        const size_t idx = base + (size_t)b * row_stride4;
        float4 v = __ldcs(&x4[idx]);          // evict-first load (touched once)
        v.x += p.x;
        v.y += p.y;
        v.z += p.z;
        v.w += p.w;
        __stcs(&o4[idx], v);                  // streaming store
    }
}

extern "C" void kernel_launch(void* const* d_in, const int* in_sizes, int n_in,
                              void* d_out, int out_size) {
    const float* x = (const float*)d_in[0];
    float* out = (float*)d_out;
    dim3 grid(PE_T, PE_BY);
    pe_add_kernel<<<grid, 256>>>(x, out);
}